// round 15
// baseline (speedup 1.0000x reference)
#include <cuda_runtime.h>
#include <cuda_fp16.h>
#include <math.h>
#include <stdint.h>

#define NTOK 8192
#define DDIM 1024
#define NSEM 8192
#define NLRN 128
#define NCB  8320           // NSEM + NLRN = 65 * 128 exactly
#define NXT  65             // column tiles (exact, no padding)
#define NCAND (NXT * 2)     // 130 top-2-per-tile candidates per row
#define NTILES (64 * 65)    // 4160
#define NPC   304           // persistent CTAs (2/SM x 152 SMs)

#define TILE_M 128
#define TILE_N 128
#define BK     64           // fp16 elems per K-chunk (128B row)
#define NKCH   (DDIM / BK)  // 16
#define STAGES 3
#define A_BYTES (TILE_M * 128)            // 16KB
#define B_BYTES (TILE_N * 128)            // 16KB
#define STAGE_BYTES (A_BYTES + B_BYTES)   // 32KB
#define RED_BYTES 4096
#define SMEM_TOTAL (STAGES * STAGE_BYTES + RED_BYTES)  // 100KB -> 2 CTAs/SM

// ---------------- scratch (__device__ globals; no allocs) -------------------
__device__ __align__(128) float  g_xn[(size_t)NTOK * DDIM];
__device__ __align__(128) float  g_cb[(size_t)NCB * DDIM];
__device__ __align__(128) __half g_Ah[(size_t)NTOK * DDIM];
__device__ __align__(128) __half g_Bh[(size_t)NCB * DDIM];
__device__ float g_p2val[(size_t)NTOK * NCAND];
__device__ int   g_p2col[(size_t)NTOK * NCAND];
__device__ float g_rowloss[NTOK];
__device__ int   g_idx[NTOK];
__device__ unsigned g_done;     // zero-initialized; reset by last block each run

// ---------------- PTX helpers ----------------------------------------------
__device__ __forceinline__ uint32_t smem_u32(const void* p) {
    uint32_t a;
    asm("{ .reg .u64 t; cvta.to.shared.u64 t, %1; cvt.u32.u64 %0, t; }" : "=r"(a) : "l"(p));
    return a;
}
__device__ __forceinline__ uint32_t sw128(uint32_t x) { return x ^ ((x >> 3) & 0x70); }

__device__ __forceinline__ void cp_async16(uint32_t dst, const void* src) {
    asm volatile("cp.async.cg.shared.global [%0], [%1], 16;" :: "r"(dst), "l"(src) : "memory");
}
#define CP_COMMIT() asm volatile("cp.async.commit_group;" ::: "memory")
#define CP_WAIT(n)  asm volatile("cp.async.wait_group %0;" :: "n"(n) : "memory")

#define LDSM_X4(r0, r1, r2, r3, a) \
    asm volatile("ldmatrix.sync.aligned.m8n8.x4.shared.b16 {%0,%1,%2,%3}, [%4];" \
                 : "=r"(r0), "=r"(r1), "=r"(r2), "=r"(r3) : "r"(a))

#define MMA16816(c, a, b0, b1) \
    asm volatile("mma.sync.aligned.m16n8k16.row.col.f32.f16.f16.f32 " \
                 "{%0,%1,%2,%3},{%4,%5,%6,%7},{%8,%9},{%0,%1,%2,%3};" \
                 : "+f"((c)[0]), "+f"((c)[1]), "+f"((c)[2]), "+f"((c)[3]) \
                 : "r"((a)[0]), "r"((a)[1]), "r"((a)[2]), "r"((a)[3]), "r"(b0), "r"(b1))

// top-2 insert keeping (value desc, col asc) order
#define TOP2_INS(v, c, v1, c1, v2, c2) do {                                  \
    float _v = (v); int _c = (c);                                            \
    if (_v > (v1) || (_v == (v1) && _c < (c1))) {                            \
        (v2) = (v1); (c2) = (c1); (v1) = _v; (c1) = _c;                      \
    } else if (_v > (v2) || (_v == (v2) && _c < (c2))) {                     \
        (v2) = _v; (c2) = _c;                                                \
    }                                                                        \
} while (0)

// ---------------------------------------------------------------------------
// merged row L2-normalize for all three tensors -> f32 copy + fp16 copy
// ---------------------------------------------------------------------------
__global__ void norm_cast_all(const float* __restrict__ x,
                              const float* __restrict__ sem,
                              const float* __restrict__ lrn) {
    int r = blockIdx.x;
    int t = threadIdx.x;
    const float* src;
    float* fdst;
    __half* hdst;
    if (r < NTOK) {
        src = x + (size_t)r * DDIM;
        fdst = g_xn + (size_t)r * DDIM;
        hdst = g_Ah + (size_t)r * DDIM;
    } else if (r < NTOK + NSEM) {
        int q = r - NTOK;
        src = sem + (size_t)q * DDIM;
        fdst = g_cb + (size_t)q * DDIM;
        hdst = g_Bh + (size_t)q * DDIM;
    } else {
        int q = r - NTOK - NSEM;
        src = lrn + (size_t)q * DDIM;
        fdst = g_cb + (size_t)(NSEM + q) * DDIM;
        hdst = g_Bh + (size_t)(NSEM + q) * DDIM;
    }
    float4 v = ((const float4*)src)[t];
    float ss = v.x * v.x + v.y * v.y + v.z * v.z + v.w * v.w;
    #pragma unroll
    for (int o = 16; o; o >>= 1) ss += __shfl_xor_sync(0xffffffffu, ss, o);
    __shared__ float red[8];
    __shared__ float inv_s;
    if ((t & 31) == 0) red[t >> 5] = ss;
    __syncthreads();
    if (t == 0) {
        float s = 0.f;
        #pragma unroll
        for (int i = 0; i < 8; i++) s += red[i];
        inv_s = 1.0f / fmaxf(sqrtf(s), 1e-8f);
    }
    __syncthreads();
    float inv = inv_s;
    float f[4] = { v.x * inv, v.y * inv, v.z * inv, v.w * inv };
    ((float4*)fdst)[t] = *(float4*)f;
    union { __half h[4]; uint2 u; } p;
    #pragma unroll
    for (int j = 0; j < 4; j++) p.h[j] = __float2half_rn(f[j]);
    *(uint2*)(hdst + 4 * t) = p.u;
}

// ---------------------------------------------------------------------------
// STATIC-PERSISTENT fp16 mma.sync GEMM (K=1024) + fused top-2 row argmax.
// (R14 configuration — unchanged; best measured)
// ---------------------------------------------------------------------------
__device__ __forceinline__ void load_chunk(const __half* __restrict__ Ah,
                                           const __half* __restrict__ Bh,
                                           uint32_t data_base, int stage,
                                           int by, int bxe, int kc, int tid) {
    uint32_t sb = data_base + stage * STAGE_BYTES;
    const char* Ab = (const char*)Ah + (size_t)by * TILE_M * (DDIM * 2) + (size_t)kc * 128;
    const char* Bb = (const char*)Bh + (size_t)bxe * TILE_N * (DDIM * 2) + (size_t)kc * 128;
    #pragma unroll
    for (int i = 0; i < 8; i++) {
        int c = tid + i * 128;          // 0..1023
        int row = c >> 3, cg = c & 7;
        cp_async16(sb + sw128(row * 128 + cg * 16),
                   Ab + (size_t)row * (DDIM * 2) + cg * 16);
    }
    #pragma unroll
    for (int i = 0; i < 8; i++) {
        int c = tid + i * 128;
        int row = c >> 3, cg = c & 7;
        cp_async16(sb + A_BYTES + sw128(row * 128 + cg * 16),
                   Bb + (size_t)row * (DDIM * 2) + cg * 16);
    }
    CP_COMMIT();
}

__global__ void __launch_bounds__(128, 2)
gemm_mma(const __half* __restrict__ Ah, const __half* __restrict__ Bh,
         float* __restrict__ Cout) {
    extern __shared__ char smem[];
    uint32_t data_base = smem_u32(smem);
    float* bufv = (float*)(smem + STAGES * STAGE_BYTES);          // [128][2][2]
    int*   bufi = (int*)(smem + STAGES * STAGE_BYTES + 2048);     // [128][2][2]

    int tid = threadIdx.x, wid = tid >> 5, lane = tid & 31;
    int bid = blockIdx.x;
    int warp_m = wid & 1;       // 2 warps over M (64 rows each)
    int warp_n = wid >> 1;      // 2 warps over N (64 cols each)

    int rowA = lane & 15;
    int kselA = (lane >> 4) * 16;
    int rowB = (lane & 7) + ((lane >> 4) & 1) * 8;
    int kselB = ((lane >> 3) & 1) * 16;

    int nt = (NTILES - bid + NPC - 1) / NPC;   // 13 or 14 tiles
    int NKT = nt * NKCH;

    float acc[4][8][4];
    #pragma unroll
    for (int i = 0; i < 4; i++)
        #pragma unroll
        for (int j = 0; j < 8; j++)
            #pragma unroll
            for (int q = 0; q < 4; q++) acc[i][j][q] = 0.f;

    {
        int t0 = bid;
        load_chunk(Ah, Bh, data_base, 0, t0 / NXT, t0 % NXT, 0, tid);
        load_chunk(Ah, Bh, data_base, 1, t0 / NXT, t0 % NXT, 1, tid);
    }

    for (int g = 0; g < NKT; g++) {
        if (g + 1 < NKT) CP_WAIT(1); else CP_WAIT(0);
        __syncthreads();
        if (g + 2 < NKT) {
            int gi = g + 2;
            int tp = bid + (gi >> 4) * NPC;
            load_chunk(Ah, Bh, data_base, gi % STAGES, tp / NXT, tp % NXT,
                       gi & (NKCH - 1), tid);
        }
        uint32_t Ab = data_base + (g % STAGES) * STAGE_BYTES;
        uint32_t Bb = Ab + A_BYTES;
        #pragma unroll
        for (int ks = 0; ks < 4; ks++) {
            uint32_t afr[4][4];
            #pragma unroll
            for (int mt = 0; mt < 4; mt++) {
                uint32_t off = (uint32_t)(warp_m * 64 + mt * 16 + rowA) * 128
                             + ks * 32 + kselA;
                LDSM_X4(afr[mt][0], afr[mt][1], afr[mt][2], afr[mt][3], Ab + sw128(off));
            }
            uint32_t bfr[4][4];
            #pragma unroll
            for (int np = 0; np < 4; np++) {
                uint32_t off = (uint32_t)(warp_n * 64 + np * 16 + rowB) * 128
                             + ks * 32 + kselB;
                LDSM_X4(bfr[np][0], bfr[np][1], bfr[np][2], bfr[np][3], Bb + sw128(off));
            }
            #pragma unroll
            for (int mt = 0; mt < 4; mt++)
                #pragma unroll
                for (int nt2 = 0; nt2 < 8; nt2++)
                    MMA16816(acc[mt][nt2], afr[mt],
                             bfr[nt2 >> 1][(nt2 & 1) * 2], bfr[nt2 >> 1][(nt2 & 1) * 2 + 1]);
        }

        if ((g & (NKCH - 1)) == (NKCH - 1)) {
            int tcur = bid + (g >> 4) * NPC;
            int by = tcur / NXT, bxe = tcur % NXT;
            int row_base = by * TILE_M + warp_m * 64;
            int col_base = bxe * TILE_N + warp_n * 64;
            #pragma unroll
            for (int mt = 0; mt < 4; mt++) {
                int r0 = row_base + mt * 16 + (lane >> 2);
                #pragma unroll
                for (int nt2 = 0; nt2 < 8; nt2++) {
                    int c0 = col_base + nt2 * 8 + (lane & 3) * 2;
                    float2* p0 = (float2*)(Cout + (size_t)r0 * NCB + c0);
                    float2* p1 = (float2*)(Cout + (size_t)(r0 + 8) * NCB + c0);
                    *p0 = make_float2(acc[mt][nt2][0], acc[mt][nt2][1]);
                    *p1 = make_float2(acc[mt][nt2][2], acc[mt][nt2][3]);
                }
            }
            #pragma unroll
            for (int mt = 0; mt < 4; mt++) {
                #pragma unroll
                for (int h = 0; h < 2; h++) {
                    float v1 = -1e30f, v2 = -1e30f;
                    int   c1 = 0x7fffffff, c2 = 0x7fffffff;
                    #pragma unroll
                    for (int nt2 = 0; nt2 < 8; nt2++) {
                        #pragma unroll
                        for (int qq = 0; qq < 2; qq++) {
                            int colg = col_base + nt2 * 8 + (lane & 3) * 2 + qq;
                            float v = acc[mt][nt2][h * 2 + qq];
                            TOP2_INS(v, colg, v1, c1, v2, c2);
                        }
                    }
                    #pragma unroll
                    for (int off = 1; off <= 2; off <<= 1) {
                        float ov1 = __shfl_xor_sync(0xffffffffu, v1, off);
                        int   oc1 = __shfl_xor_sync(0xffffffffu, c1, off);
                        float ov2 = __shfl_xor_sync(0xffffffffu, v2, off);
                        int   oc2 = __shfl_xor_sync(0xffffffffu, c2, off);
                        TOP2_INS(ov1, oc1, v1, c1, v2, c2);
                        TOP2_INS(ov2, oc2, v1, c1, v2, c2);
                    }
                    if ((lane & 3) == 0) {
                        int rl = warp_m * 64 + mt * 16 + (lane >> 2) + h * 8;
                        bufv[(rl * 2 + warp_n) * 2 + 0] = v1;
                        bufv[(rl * 2 + warp_n) * 2 + 1] = v2;
                        bufi[(rl * 2 + warp_n) * 2 + 0] = c1;
                        bufi[(rl * 2 + warp_n) * 2 + 1] = c2;
                    }
                }
            }
            __syncthreads();
            {
                float v1 = -1e30f, v2 = -1e30f;
                int   c1 = 0x7fffffff, c2 = 0x7fffffff;
                #pragma unroll
                for (int w = 0; w < 2; w++) {
                    TOP2_INS(bufv[(tid * 2 + w) * 2 + 0], bufi[(tid * 2 + w) * 2 + 0], v1, c1, v2, c2);
                    TOP2_INS(bufv[(tid * 2 + w) * 2 + 1], bufi[(tid * 2 + w) * 2 + 1], v1, c1, v2, c2);
                }
                size_t base = ((size_t)(by * TILE_M + tid) * NXT + bxe) * 2;
                g_p2val[base + 0] = v1; g_p2val[base + 1] = v2;
                g_p2col[base + 0] = c1; g_p2col[base + 1] = c2;
            }
            __syncthreads();   // protect bufv/bufi before next tile's epilogue
            #pragma unroll
            for (int i = 0; i < 4; i++)
                #pragma unroll
                for (int j = 0; j < 8; j++)
                    #pragma unroll
                    for (int q = 0; q < 4; q++) acc[i][j][q] = 0.f;
        }
    }
}

// ---------------------------------------------------------------------------
// WARP-PER-ROW rescore + gather + fused losses. 8 rows/block, grid 1024.
// Fast path (unique in-margin candidate) is register/shfl-only.
// ---------------------------------------------------------------------------
__global__ void __launch_bounds__(256)
rescore_gather(float* __restrict__ idx_out,
               float* __restrict__ zq,
               float* __restrict__ zqst,
               float* __restrict__ scal) {
    int wid = threadIdx.x >> 5, lane = threadIdx.x & 31;
    int r = blockIdx.x * 8 + wid;

    // load candidate list (130 entries, 5 rounds of 32)
    float v[5]; int c[5];
    #pragma unroll
    for (int i = 0; i < 5; i++) {
        int idx = lane + i * 32;
        if (idx < NCAND) {
            v[i] = g_p2val[(size_t)r * NCAND + idx];
            c[i] = g_p2col[(size_t)r * NCAND + idx];
        } else { v[i] = -1e30f; c[i] = 0x7fffffff; }
    }
    float m = v[0];
    #pragma unroll
    for (int i = 1; i < 5; i++) m = fmaxf(m, v[i]);
    #pragma unroll
    for (int o = 16; o; o >>= 1) m = fmaxf(m, __shfl_xor_sync(0xffffffffu, m, o));

    unsigned bmask[5];
    int cnt = 0;
    #pragma unroll
    for (int i = 0; i < 5; i++) {
        bool ok = (v[i] >= m - 1.5e-4f) && (c[i] < NCB);
        bmask[i] = __ballot_sync(0xffffffffu, ok);
        cnt += __popc(bmask[i]);
    }

    const float4* xrow = (const float4*)(g_xn + (size_t)r * DDIM);
    int bestc = 0x7fffffff;
    double bestv;
    if (cnt == 1) {
        #pragma unroll
        for (int i = 0; i < 5; i++) {
            if (bmask[i]) {
                int src = __ffs(bmask[i]) - 1;
                bestc = __shfl_sync(0xffffffffu, c[i], src);
            }
        }
        bestv = (double)m;
    } else {
        bestv = -1e30;
        #pragma unroll
        for (int i = 0; i < 5; i++) {
            unsigned b = bmask[i];
            while (b) {
                int src = __ffs(b) - 1; b &= b - 1;
                int cc = __shfl_sync(0xffffffffu, c[i], src);
                const float4* crow = (const float4*)(g_cb + (size_t)cc * DDIM);
                double d = 0.0;
                #pragma unroll
                for (int k = 0; k < 8; k++) {
                    float4 x4 = xrow[k * 32 + lane];
                    float4 c4 = crow[k * 32 + lane];
                    d += (double)x4.x * c4.x + (double)x4.y * c4.y
                       + (double)x4.z * c4.z + (double)x4.w * c4.w;
                }
                #pragma unroll
                for (int o = 16; o; o >>= 1) d += __shfl_xor_sync(0xffffffffu, d, o);
                if (d > bestv || (d == bestv && cc < bestc)) { bestv = d; bestc = cc; }
            }
        }
    }

    if (lane == 0) {
        idx_out[r]   = (float)bestc;
        g_idx[r]     = bestc;
        g_rowloss[r] = 1.0f - (float)bestv;
    }
    const float4* crow = (const float4*)(g_cb + (size_t)bestc * DDIM);
    float4* zqr = (float4*)(zq + (size_t)r * DDIM);
    float4* zsr = (float4*)(zqst + (size_t)r * DDIM);
    #pragma unroll
    for (int k = 0; k < 8; k++) {
        float4 c4 = crow[k * 32 + lane];
        float4 x4 = xrow[k * 32 + lane];
        zqr[k * 32 + lane] = c4;
        zsr[k * 32 + lane] = make_float4(x4.x + (c4.x - x4.x), x4.y + (c4.y - x4.y),
                                         x4.z + (c4.z - x4.z), x4.w + (c4.w - x4.w));
    }

    // ---- fused loss reduction: last block does it ----
    __shared__ int slast;
    __syncthreads();
    if (threadIdx.x == 0) {
        __threadfence();
        unsigned prev = atomicAdd(&g_done, 1u);
        slast = (prev == gridDim.x - 1) ? 1 : 0;
    }
    __syncthreads();
    if (slast) {
        __threadfence();
        __shared__ float scom[256];
        __shared__ float svq[256];
        __shared__ int   scnt[256];
        float cm = 0.f, vq = 0.f; int cnt2 = 0;
        for (int rr = threadIdx.x; rr < NTOK; rr += 256) {
            float l = g_rowloss[rr];
            cm += l;
            if (g_idx[rr] >= NSEM) { vq += l; cnt2++; }
        }
        int t = threadIdx.x;
        scom[t] = cm; svq[t] = vq; scnt[t] = cnt2;
        __syncthreads();
        #pragma unroll
        for (int off = 128; off; off >>= 1) {
            if (t < off) {
                scom[t] += scom[t + off];
                svq[t]  += svq[t + off];
                scnt[t] += scnt[t + off];
            }
            __syncthreads();
        }
        if (t == 0) {
            float commitment = scom[0] / (float)NTOK;
            float vql = svq[0] / ((float)scnt[0] + 1e-6f);
            scal[0] = vql;
            scal[1] = commitment;
            scal[2] = vql + 0.25f * commitment;
            g_done = 0;              // reset for next graph replay
        }
    }
}

// ---------------------------------------------------------------------------
extern "C" void kernel_launch(void* const* d_in, const int* in_sizes, int n_in,
                              void* d_out, int out_size) {
    const float* x   = (const float*)d_in[0];
    const float* sem = (const float*)d_in[1];
    const float* lrn = (const float*)d_in[2];
    float* out = (float*)d_out;

    float* logits = out;
    float* idxf   = out  + (size_t)NTOK * NCB;
    float* zq     = idxf + NTOK;
    float* zqst   = zq   + (size_t)NTOK * DDIM;
    float* scal   = zqst + (size_t)NTOK * DDIM;

    __half *p_A, *p_B;
    cudaGetSymbolAddress((void**)&p_A, g_Ah);
    cudaGetSymbolAddress((void**)&p_B, g_Bh);

    norm_cast_all<<<NTOK + NSEM + NLRN, 256>>>(x, sem, lrn);     // 0

    cudaFuncSetAttribute(gemm_mma, cudaFuncAttributeMaxDynamicSharedMemorySize, SMEM_TOTAL);
    gemm_mma<<<NPC, 128, SMEM_TOTAL>>>(p_A, p_B, logits);        // 1

    rescore_gather<<<NTOK / 8, 256>>>(idxf, zq, zqst, scal);     // 2
}

// round 16
// speedup vs baseline: 1.0175x; 1.0175x over previous
#include <cuda_runtime.h>
#include <cuda_fp16.h>
#include <math.h>
#include <stdint.h>

#define NTOK 8192
#define DDIM 1024
#define NSEM 8192
#define NLRN 128
#define NCB  8320           // NSEM + NLRN = 65 * 128 exactly
#define NXT  65             // column tiles (exact, no padding)
#define NCAND (NXT * 2)     // 130 top-2-per-tile candidates per row
#define NTILES (64 * 65)    // 4160
#define NPC   304           // persistent CTAs (2/SM x 152 SMs)

#define TILE_M 128
#define TILE_N 128
#define BK     64           // fp16 elems per K-chunk (128B row)
#define NKCH   (DDIM / BK)  // 16
#define STAGES 3
#define A_BYTES (TILE_M * 128)            // 16KB
#define B_BYTES (TILE_N * 128)            // 16KB
#define STAGE_BYTES (A_BYTES + B_BYTES)   // 32KB
#define RED_BYTES 4096
#define SMEM_TOTAL (STAGES * STAGE_BYTES + RED_BYTES)  // 100KB -> 2 CTAs/SM

// ---------------- scratch (__device__ globals; no allocs) -------------------
__device__ __align__(128) float  g_xn[(size_t)NTOK * DDIM];
__device__ __align__(128) float  g_cb[(size_t)NCB * DDIM];
__device__ __align__(128) __half g_Ah[(size_t)NTOK * DDIM];
__device__ __align__(128) __half g_Bh[(size_t)NCB * DDIM];
__device__ float g_p2val[(size_t)NTOK * NCAND];
__device__ int   g_p2col[(size_t)NTOK * NCAND];
__device__ float g_rowloss[NTOK];
__device__ int   g_idx[NTOK];
__device__ unsigned g_done;     // zero-initialized; reset by last block each run

// ---------------- PTX helpers ----------------------------------------------
__device__ __forceinline__ uint32_t smem_u32(const void* p) {
    uint32_t a;
    asm("{ .reg .u64 t; cvta.to.shared.u64 t, %1; cvt.u32.u64 %0, t; }" : "=r"(a) : "l"(p));
    return a;
}
__device__ __forceinline__ uint32_t sw128(uint32_t x) { return x ^ ((x >> 3) & 0x70); }

__device__ __forceinline__ void cp_async16(uint32_t dst, const void* src) {
    asm volatile("cp.async.cg.shared.global [%0], [%1], 16;" :: "r"(dst), "l"(src) : "memory");
}
#define CP_COMMIT() asm volatile("cp.async.commit_group;" ::: "memory")
#define CP_WAIT(n)  asm volatile("cp.async.wait_group %0;" :: "n"(n) : "memory")

#define LDSM_X4(r0, r1, r2, r3, a) \
    asm volatile("ldmatrix.sync.aligned.m8n8.x4.shared.b16 {%0,%1,%2,%3}, [%4];" \
                 : "=r"(r0), "=r"(r1), "=r"(r2), "=r"(r3) : "r"(a))

#define MMA16816(c, a, b0, b1) \
    asm volatile("mma.sync.aligned.m16n8k16.row.col.f32.f16.f16.f32 " \
                 "{%0,%1,%2,%3},{%4,%5,%6,%7},{%8,%9},{%0,%1,%2,%3};" \
                 : "+f"((c)[0]), "+f"((c)[1]), "+f"((c)[2]), "+f"((c)[3]) \
                 : "r"((a)[0]), "r"((a)[1]), "r"((a)[2]), "r"((a)[3]), "r"(b0), "r"(b1))

// top-2 insert keeping (value desc, col asc) order
#define TOP2_INS(v, c, v1, c1, v2, c2) do {                                  \
    float _v = (v); int _c = (c);                                            \
    if (_v > (v1) || (_v == (v1) && _c < (c1))) {                            \
        (v2) = (v1); (c2) = (c1); (v1) = _v; (c1) = _c;                      \
    } else if (_v > (v2) || (_v == (v2) && _c < (c2))) {                     \
        (v2) = _v; (c2) = _c;                                                \
    }                                                                        \
} while (0)

// ---------------------------------------------------------------------------
// merged row L2-normalize for all three tensors -> f32 copy + fp16 copy
// ---------------------------------------------------------------------------
__global__ void norm_cast_all(const float* __restrict__ x,
                              const float* __restrict__ sem,
                              const float* __restrict__ lrn) {
    int r = blockIdx.x;
    int t = threadIdx.x;
    const float* src;
    float* fdst;
    __half* hdst;
    if (r < NTOK) {
        src = x + (size_t)r * DDIM;
        fdst = g_xn + (size_t)r * DDIM;
        hdst = g_Ah + (size_t)r * DDIM;
    } else if (r < NTOK + NSEM) {
        int q = r - NTOK;
        src = sem + (size_t)q * DDIM;
        fdst = g_cb + (size_t)q * DDIM;
        hdst = g_Bh + (size_t)q * DDIM;
    } else {
        int q = r - NTOK - NSEM;
        src = lrn + (size_t)q * DDIM;
        fdst = g_cb + (size_t)(NSEM + q) * DDIM;
        hdst = g_Bh + (size_t)(NSEM + q) * DDIM;
    }
    float4 v = ((const float4*)src)[t];
    float ss = v.x * v.x + v.y * v.y + v.z * v.z + v.w * v.w;
    #pragma unroll
    for (int o = 16; o; o >>= 1) ss += __shfl_xor_sync(0xffffffffu, ss, o);
    __shared__ float red[8];
    __shared__ float inv_s;
    if ((t & 31) == 0) red[t >> 5] = ss;
    __syncthreads();
    if (t == 0) {
        float s = 0.f;
        #pragma unroll
        for (int i = 0; i < 8; i++) s += red[i];
        inv_s = 1.0f / fmaxf(sqrtf(s), 1e-8f);
    }
    __syncthreads();
    float inv = inv_s;
    float f[4] = { v.x * inv, v.y * inv, v.z * inv, v.w * inv };
    ((float4*)fdst)[t] = *(float4*)f;
    union { __half h[4]; uint2 u; } p;
    #pragma unroll
    for (int j = 0; j < 4; j++) p.h[j] = __float2half_rn(f[j]);
    *(uint2*)(hdst + 4 * t) = p.u;
}

// ---------------------------------------------------------------------------
// STATIC-PERSISTENT fp16 mma.sync GEMM (K=1024) + fused top-2 row argmax.
// grid 304 (2/SM); CTA b owns tiles b, b+304, ... in ONE continuous 3-stage
// cp.async pipeline; epilogues overlap next tile's loads.
// CTA 128x128, 4 warps (2x2), warp tile 64x64. (R14-best, unchanged)
// ---------------------------------------------------------------------------
__device__ __forceinline__ void load_chunk(const __half* __restrict__ Ah,
                                           const __half* __restrict__ Bh,
                                           uint32_t data_base, int stage,
                                           int by, int bxe, int kc, int tid) {
    uint32_t sb = data_base + stage * STAGE_BYTES;
    const char* Ab = (const char*)Ah + (size_t)by * TILE_M * (DDIM * 2) + (size_t)kc * 128;
    const char* Bb = (const char*)Bh + (size_t)bxe * TILE_N * (DDIM * 2) + (size_t)kc * 128;
    #pragma unroll
    for (int i = 0; i < 8; i++) {
        int c = tid + i * 128;          // 0..1023
        int row = c >> 3, cg = c & 7;
        cp_async16(sb + sw128(row * 128 + cg * 16),
                   Ab + (size_t)row * (DDIM * 2) + cg * 16);
    }
    #pragma unroll
    for (int i = 0; i < 8; i++) {
        int c = tid + i * 128;
        int row = c >> 3, cg = c & 7;
        cp_async16(sb + A_BYTES + sw128(row * 128 + cg * 16),
                   Bb + (size_t)row * (DDIM * 2) + cg * 16);
    }
    CP_COMMIT();
}

__global__ void __launch_bounds__(128, 2)
gemm_mma(const __half* __restrict__ Ah, const __half* __restrict__ Bh,
         float* __restrict__ Cout) {
    extern __shared__ char smem[];
    uint32_t data_base = smem_u32(smem);
    float* bufv = (float*)(smem + STAGES * STAGE_BYTES);          // [128][2][2]
    int*   bufi = (int*)(smem + STAGES * STAGE_BYTES + 2048);     // [128][2][2]

    int tid = threadIdx.x, wid = tid >> 5, lane = tid & 31;
    int bid = blockIdx.x;
    int warp_m = wid & 1;       // 2 warps over M (64 rows each)
    int warp_n = wid >> 1;      // 2 warps over N (64 cols each)

    int rowA = lane & 15;
    int kselA = (lane >> 4) * 16;
    int rowB = (lane & 7) + ((lane >> 4) & 1) * 8;
    int kselB = ((lane >> 3) & 1) * 16;

    int nt = (NTILES - bid + NPC - 1) / NPC;   // 13 or 14 tiles
    int NKT = nt * NKCH;

    float acc[4][8][4];
    #pragma unroll
    for (int i = 0; i < 4; i++)
        #pragma unroll
        for (int j = 0; j < 8; j++)
            #pragma unroll
            for (int q = 0; q < 4; q++) acc[i][j][q] = 0.f;

    {
        int t0 = bid;
        load_chunk(Ah, Bh, data_base, 0, t0 / NXT, t0 % NXT, 0, tid);
        load_chunk(Ah, Bh, data_base, 1, t0 / NXT, t0 % NXT, 1, tid);
    }

    for (int g = 0; g < NKT; g++) {
        if (g + 1 < NKT) CP_WAIT(1); else CP_WAIT(0);
        __syncthreads();
        if (g + 2 < NKT) {
            int gi = g + 2;
            int tp = bid + (gi >> 4) * NPC;
            load_chunk(Ah, Bh, data_base, gi % STAGES, tp / NXT, tp % NXT,
                       gi & (NKCH - 1), tid);
        }
        uint32_t Ab = data_base + (g % STAGES) * STAGE_BYTES;
        uint32_t Bb = Ab + A_BYTES;
        #pragma unroll
        for (int ks = 0; ks < 4; ks++) {
            uint32_t afr[4][4];
            #pragma unroll
            for (int mt = 0; mt < 4; mt++) {
                uint32_t off = (uint32_t)(warp_m * 64 + mt * 16 + rowA) * 128
                             + ks * 32 + kselA;
                LDSM_X4(afr[mt][0], afr[mt][1], afr[mt][2], afr[mt][3], Ab + sw128(off));
            }
            uint32_t bfr[4][4];
            #pragma unroll
            for (int np = 0; np < 4; np++) {
                uint32_t off = (uint32_t)(warp_n * 64 + np * 16 + rowB) * 128
                             + ks * 32 + kselB;
                LDSM_X4(bfr[np][0], bfr[np][1], bfr[np][2], bfr[np][3], Bb + sw128(off));
            }
            #pragma unroll
            for (int mt = 0; mt < 4; mt++)
                #pragma unroll
                for (int nt2 = 0; nt2 < 8; nt2++)
                    MMA16816(acc[mt][nt2], afr[mt],
                             bfr[nt2 >> 1][(nt2 & 1) * 2], bfr[nt2 >> 1][(nt2 & 1) * 2 + 1]);
        }

        if ((g & (NKCH - 1)) == (NKCH - 1)) {
            // ============ epilogue for tile bid + (g>>4)*NPC; overlaps next loads
            int tcur = bid + (g >> 4) * NPC;
            int by = tcur / NXT, bxe = tcur % NXT;
            int row_base = by * TILE_M + warp_m * 64;
            int col_base = bxe * TILE_N + warp_n * 64;
            #pragma unroll
            for (int mt = 0; mt < 4; mt++) {
                int r0 = row_base + mt * 16 + (lane >> 2);
                #pragma unroll
                for (int nt2 = 0; nt2 < 8; nt2++) {
                    int c0 = col_base + nt2 * 8 + (lane & 3) * 2;
                    float2* p0 = (float2*)(Cout + (size_t)r0 * NCB + c0);
                    float2* p1 = (float2*)(Cout + (size_t)(r0 + 8) * NCB + c0);
                    *p0 = make_float2(acc[mt][nt2][0], acc[mt][nt2][1]);
                    *p1 = make_float2(acc[mt][nt2][2], acc[mt][nt2][3]);
                }
            }
            #pragma unroll
            for (int mt = 0; mt < 4; mt++) {
                #pragma unroll
                for (int h = 0; h < 2; h++) {
                    float v1 = -1e30f, v2 = -1e30f;
                    int   c1 = 0x7fffffff, c2 = 0x7fffffff;
                    #pragma unroll
                    for (int nt2 = 0; nt2 < 8; nt2++) {
                        #pragma unroll
                        for (int qq = 0; qq < 2; qq++) {
                            int colg = col_base + nt2 * 8 + (lane & 3) * 2 + qq;
                            float v = acc[mt][nt2][h * 2 + qq];
                            TOP2_INS(v, colg, v1, c1, v2, c2);
                        }
                    }
                    #pragma unroll
                    for (int off = 1; off <= 2; off <<= 1) {
                        float ov1 = __shfl_xor_sync(0xffffffffu, v1, off);
                        int   oc1 = __shfl_xor_sync(0xffffffffu, c1, off);
                        float ov2 = __shfl_xor_sync(0xffffffffu, v2, off);
                        int   oc2 = __shfl_xor_sync(0xffffffffu, c2, off);
                        TOP2_INS(ov1, oc1, v1, c1, v2, c2);
                        TOP2_INS(ov2, oc2, v1, c1, v2, c2);
                    }
                    if ((lane & 3) == 0) {
                        int rl = warp_m * 64 + mt * 16 + (lane >> 2) + h * 8;
                        bufv[(rl * 2 + warp_n) * 2 + 0] = v1;
                        bufv[(rl * 2 + warp_n) * 2 + 1] = v2;
                        bufi[(rl * 2 + warp_n) * 2 + 0] = c1;
                        bufi[(rl * 2 + warp_n) * 2 + 1] = c2;
                    }
                }
            }
            __syncthreads();
            {
                float v1 = -1e30f, v2 = -1e30f;
                int   c1 = 0x7fffffff, c2 = 0x7fffffff;
                #pragma unroll
                for (int w = 0; w < 2; w++) {
                    TOP2_INS(bufv[(tid * 2 + w) * 2 + 0], bufi[(tid * 2 + w) * 2 + 0], v1, c1, v2, c2);
                    TOP2_INS(bufv[(tid * 2 + w) * 2 + 1], bufi[(tid * 2 + w) * 2 + 1], v1, c1, v2, c2);
                }
                size_t base = ((size_t)(by * TILE_M + tid) * NXT + bxe) * 2;
                g_p2val[base + 0] = v1; g_p2val[base + 1] = v2;
                g_p2col[base + 0] = c1; g_p2col[base + 1] = c2;
            }
            __syncthreads();   // protect bufv/bufi before next tile's epilogue
            #pragma unroll
            for (int i = 0; i < 4; i++)
                #pragma unroll
                for (int j = 0; j < 8; j++)
                    #pragma unroll
                    for (int q = 0; q < 4; q++) acc[i][j][q] = 0.f;
        }
    }
}

// ---------------------------------------------------------------------------
// exact rescoring of near-max candidates + gather z_q / z_q_st + fused losses.
// (R14 block-per-row version — measured fastest.)
// FAST PATH: unique in-margin candidate IS the exact argmax.
// ---------------------------------------------------------------------------
__global__ void rescore_gather(float* __restrict__ idx_out,
                               float* __restrict__ zq,
                               float* __restrict__ zqst,
                               float* __restrict__ scal) {
    int r = blockIdx.x;
    int t = threadIdx.x;
    __shared__ float  cval[NCAND];
    __shared__ int    ccol[NCAND];
    __shared__ float  smax;
    __shared__ int    ncand;
    __shared__ int    clist[NCAND];
    __shared__ double dred[256];
    __shared__ double sbest;
    __shared__ int    sbestc;
    __shared__ int    slast;

    if (t < NCAND) {
        cval[t] = g_p2val[(size_t)r * NCAND + t];
        ccol[t] = g_p2col[(size_t)r * NCAND + t];
    }
    if (t == 0) ncand = 0;
    __syncthreads();
    if (t == 0) {
        float m = -1e30f;
        #pragma unroll
        for (int i = 0; i < NCAND; i++) m = fmaxf(m, cval[i]);
        smax = m;
    }
    __syncthreads();
    if (t < NCAND && cval[t] >= smax - 1.5e-4f && ccol[t] < NCB) {
        int s = atomicAdd(&ncand, 1);
        clist[s] = ccol[t];
    }
    __syncthreads();

    int n = ncand;
    double bestv; int bestc;
    const float4 xv = ((const float4*)(g_xn + (size_t)r * DDIM))[t];
    if (n == 1) {
        bestc = clist[0];
        bestv = (double)smax;
    } else {
        bestv = -1e30; bestc = 0x7fffffff;
        for (int i = 0; i < n; i++) {
            int c = clist[i];
            const float4 cv = ((const float4*)(g_cb + (size_t)c * DDIM))[t];
            double d = (double)xv.x * cv.x + (double)xv.y * cv.y
                     + (double)xv.z * cv.z + (double)xv.w * cv.w;
            dred[t] = d;
            __syncthreads();
            #pragma unroll
            for (int off = 128; off; off >>= 1) {
                if (t < off) dred[t] += dred[t + off];
                __syncthreads();
            }
            double tot = dred[0];
            __syncthreads();
            if (tot > bestv || (tot == bestv && c < bestc)) { bestv = tot; bestc = c; }
        }
        if (t == 0) { sbest = bestv; sbestc = bestc; }
        __syncthreads();
        bestc = sbestc; bestv = sbest;
    }

    if (t == 0) {
        idx_out[r]   = (float)bestc;
        g_idx[r]     = bestc;
        g_rowloss[r] = 1.0f - (float)bestv;
    }
    const float4 cv = ((const float4*)(g_cb + (size_t)bestc * DDIM))[t];
    ((float4*)(zq + (size_t)r * DDIM))[t] = cv;
    float4 st = make_float4(xv.x + (cv.x - xv.x), xv.y + (cv.y - xv.y),
                            xv.z + (cv.z - xv.z), xv.w + (cv.w - xv.w));
    ((float4*)(zqst + (size_t)r * DDIM))[t] = st;

    // ---- fused loss reduction: last block to finish does it ----
    __syncthreads();
    if (t == 0) {
        __threadfence();
        unsigned prev = atomicAdd(&g_done, 1u);
        slast = (prev == NTOK - 1) ? 1 : 0;
    }
    __syncthreads();
    if (slast) {
        __threadfence();
        __shared__ float scom[256];
        __shared__ float svq[256];
        __shared__ int   scnt[256];
        float cm = 0.f, vq = 0.f; int cnt = 0;
        for (int rr = t; rr < NTOK; rr += 256) {
            float l = g_rowloss[rr];
            cm += l;
            if (g_idx[rr] >= NSEM) { vq += l; cnt++; }
        }
        scom[t] = cm; svq[t] = vq; scnt[t] = cnt;
        __syncthreads();
        #pragma unroll
        for (int off = 128; off; off >>= 1) {
            if (t < off) {
                scom[t] += scom[t + off];
                svq[t]  += svq[t + off];
                scnt[t] += scnt[t + off];
            }
            __syncthreads();
        }
        if (t == 0) {
            float commitment = scom[0] / (float)NTOK;
            float vql = svq[0] / ((float)scnt[0] + 1e-6f);
            scal[0] = vql;
            scal[1] = commitment;
            scal[2] = vql + 0.25f * commitment;
            g_done = 0;              // reset for next graph replay
        }
    }
}

// ---------------------------------------------------------------------------
extern "C" void kernel_launch(void* const* d_in, const int* in_sizes, int n_in,
                              void* d_out, int out_size) {
    const float* x   = (const float*)d_in[0];
    const float* sem = (const float*)d_in[1];
    const float* lrn = (const float*)d_in[2];
    float* out = (float*)d_out;

    float* logits = out;
    float* idxf   = out  + (size_t)NTOK * NCB;
    float* zq     = idxf + NTOK;
    float* zqst   = zq   + (size_t)NTOK * DDIM;
    float* scal   = zqst + (size_t)NTOK * DDIM;

    __half *p_A, *p_B;
    cudaGetSymbolAddress((void**)&p_A, g_Ah);
    cudaGetSymbolAddress((void**)&p_B, g_Bh);

    norm_cast_all<<<NTOK + NSEM + NLRN, 256>>>(x, sem, lrn);     // 0

    cudaFuncSetAttribute(gemm_mma, cudaFuncAttributeMaxDynamicSharedMemorySize, SMEM_TOTAL);
    gemm_mma<<<NPC, 128, SMEM_TOTAL>>>(p_A, p_B, logits);        // 1

    rescore_gather<<<NTOK, 256>>>(idxf, zq, zqst, scal);         // 2
}